// round 4
// baseline (speedup 1.0000x reference)
#include <cuda_runtime.h>
#include <cuda_bf16.h>
#include <math.h>

// Problem dims (fixed by the reference)
#define NP      128      // proposals
#define NB      16       // neighbors per proposal
#define KK      64       // knn per node
#define LL      1024     // NB*KK flattened group size
#define MM      450      // FINEMATCH_MAX_POINT
#define DD      256      // feature dim
#define NPTS_C  20000

// Scratch (device globals: allocation-free, graph-capture safe)
__device__ int g_valid[NP * LL];   // per-proposal compacted valid positions (stable order)
__device__ int g_n[NP];            // per-proposal valid count

// ---------------------------------------------------------------------------
// Kernel 1: per-proposal mask evaluation + stable stream compaction.
// 128 blocks x 1024 threads; one thread per flattened position j.
// Bool inputs arrive as 32-bit words; nonzero test handles int32 or float32.
// Stable order (ascending j) matches jnp.argsort(stable) of !mask.
// ---------------------------------------------------------------------------
__global__ void __launch_bounds__(1024) compact_kernel(
    const unsigned int*  __restrict__ nb_mask,     // [P, NB] bool-as-u32
    const int*           __restrict__ seed_idx,    // [P, NB] int32
    const unsigned int*  __restrict__ knn_masks)   // [NNODES, K] bool-as-u32
{
    const int p = blockIdx.x;
    const int j = threadIdx.x;                 // 0..1023
    const int nb = j >> 6;                     // j / K
    const int kk = j & 63;                     // j % K

    const int node = seed_idx[p * NB + nb];
    const bool m = (knn_masks[node * KK + kk] != 0u) && (nb_mask[p * NB + nb] != 0u);

    const unsigned ball = __ballot_sync(0xffffffffu, m);
    const int lane = j & 31;
    const int warp = j >> 5;                   // 0..31
    const int wpre = __popc(ball & ((1u << lane) - 1u));

    __shared__ int wsum[32];
    __shared__ int woff[32];
    if (lane == 0) wsum[warp] = __popc(ball);
    __syncthreads();

    if (warp == 0) {
        int v = wsum[lane];
        int s = v;
        #pragma unroll
        for (int d = 1; d < 32; d <<= 1) {
            int t = __shfl_up_sync(0xffffffffu, s, d);
            if (lane >= d) s += t;
        }
        woff[lane] = s - v;                    // exclusive prefix of warp totals
        if (lane == 31) g_n[p] = s;            // total valid count
    }
    __syncthreads();

    if (m) g_valid[p * LL + woff[warp] + wpre] = j;
}

// ---------------------------------------------------------------------------
// Kernel 2: resample + gather. One warp per output row (p, i).
// Output layout (float32, concatenated flat):
//   [0,              P*M*3)            points
//   [P*M*3,          P*M*3 + P*M*D)    feats
//   [P*M*3 + P*M*D,  end)              mask (1.0f / 0.0f)
// Resample index: XLA rewrites (i/M)*n -> (i*n)/M; i*n < 2^24 is exact in
// fp32, so a SINGLE IEEE division (exact at integer quotients) replicates the
// reference bit-exactly. (Double-rounded div-then-mul mismatched ~27 rows.)
// Feats copy: 256 floats = 64 float4; each lane moves 2 float4.
// ---------------------------------------------------------------------------
__global__ void __launch_bounds__(128) gather_kernel(
    const int*   __restrict__ seed_idx,     // [P, NB]
    const float* __restrict__ knn_points,   // [NNODES, K, 3]
    const int*   __restrict__ knn_idx,      // [NNODES, K]
    const float* __restrict__ feats,        // [NPTS, D]
    float*       __restrict__ out)
{
    const int p = blockIdx.x;
    const int i = blockIdx.y * 4 + (threadIdx.x >> 5);
    if (i >= MM) return;
    const int lane = threadIdx.x & 31;

    const size_t FEATS_OFF = (size_t)NP * MM * 3;
    const size_t MASK_OFF  = FEATS_OFF + (size_t)NP * MM * DD;
    const size_t row = (size_t)p * MM + i;

    const int n = g_n[p];
    const int nm = (n < MM) ? n : MM;

    float4* dst = (float4*)(out + FEATS_OFF + row * DD);

    if (i < nm) {
        int local;
        if (n > MM) {
            // single-rounded fp32: floor((i*n) / 450) ; i*n < 2^24 so exact
            local = __float2int_rd(__fdiv_rn((float)(i * n), (float)MM));
        } else {
            local = i;
        }
        if (local > LL - 1) local = LL - 1;
        if (local < 0) local = 0;

        const int pos  = g_valid[p * LL + local];
        const int nb   = pos >> 6;
        const int kk   = pos & 63;
        const int node = seed_idx[p * NB + nb];
        const int gk   = node * KK + kk;
        const int fidx = knn_idx[gk];

        if (lane < 3) out[row * 3 + lane] = knn_points[gk * 3 + lane];
        if (lane == 0) out[MASK_OFF + row] = 1.0f;

        if (fidx >= 0 && fidx < NPTS_C) {
            const float4* src = (const float4*)(feats + (size_t)fidx * DD);
            dst[lane]      = __ldg(src + lane);
            dst[lane + 32] = __ldg(src + lane + 32);
        } else {
            const float4 z = make_float4(0.f, 0.f, 0.f, 0.f);
            dst[lane] = z;
            dst[lane + 32] = z;
        }
    } else {
        if (lane < 3) out[row * 3 + lane] = 0.0f;
        if (lane == 0) out[MASK_OFF + row] = 0.0f;
        const float4 z = make_float4(0.f, 0.f, 0.f, 0.f);
        dst[lane] = z;
        dst[lane + 32] = z;
    }
}

extern "C" void kernel_launch(void* const* d_in, const int* in_sizes, int n_in,
                              void* d_out, int out_size)
{
    // metadata order (= setup_inputs dict order):
    // 0: ref_node_neighbor_mask   (P, NB)        bool -> u32
    // 1: ref_seed_neighbor_indices(P, NB)        int32
    // 2: ref_node_knn_masks       (NNODES, K)    bool -> u32
    // 3: ref_node_knn_points      (NNODES, K, 3) float32
    // 4: ref_node_knn_indices     (NNODES, K)    int32
    // 5: ref_feats_m              (NPTS, D)      float32
    const unsigned int*  nb_mask    = (const unsigned int*)d_in[0];
    const int*           seed_idx   = (const int*)d_in[1];
    const unsigned int*  knn_masks  = (const unsigned int*)d_in[2];
    const float*         knn_points = (const float*)d_in[3];
    const int*           knn_idx    = (const int*)d_in[4];
    const float*         feats      = (const float*)d_in[5];
    float* out = (float*)d_out;

    compact_kernel<<<NP, 1024>>>(nb_mask, seed_idx, knn_masks);

    dim3 grid(NP, (MM + 3) / 4);   // 4 warps/block, 1 warp per output row
    gather_kernel<<<grid, 128>>>(seed_idx, knn_points, knn_idx, feats, out);
}

// round 5
// speedup vs baseline: 1.0818x; 1.0818x over previous
#include <cuda_runtime.h>
#include <cuda_bf16.h>
#include <math.h>

// Problem dims (fixed by the reference)
#define NP      128      // proposals
#define NB      16       // neighbors per proposal
#define KK      64       // knn per node
#define LL      1024     // NB*KK flattened group size
#define MM      450      // FINEMATCH_MAX_POINT
#define DD      256      // feature dim
#define NPTS_C  20000

// Scratch (device globals: allocation-free, graph-capture safe)
// Per valid slot: {fidx, x_bits, y_bits, z_bits} — fully resolved record so the
// gather kernel has a 1-load index chain instead of 3 dependent hops.
__device__ int4 g_rec[NP * LL];
__device__ int  g_n[NP];

// ---------------------------------------------------------------------------
// Kernel 1: mask eval + stable compaction + index/point resolution.
// 128 blocks x 1024 threads; thread j handles flattened position j.
// Stable order (ascending j) matches jnp.argsort(stable) of !mask.
// ---------------------------------------------------------------------------
__global__ void __launch_bounds__(1024) compact_kernel(
    const unsigned int*  __restrict__ nb_mask,     // [P, NB] bool-as-u32
    const int*           __restrict__ seed_idx,    // [P, NB] int32
    const unsigned int*  __restrict__ knn_masks,   // [NNODES, K] bool-as-u32
    const int*           __restrict__ knn_idx,     // [NNODES, K]
    const float*         __restrict__ knn_points)  // [NNODES, K, 3]
{
    const int p = blockIdx.x;
    const int j = threadIdx.x;                 // 0..1023
    const int nb = j >> 6;                     // j / K
    const int kk = j & 63;                     // j % K

    const int node = seed_idx[p * NB + nb];
    const int gk   = node * KK + kk;
    const bool m = (knn_masks[gk] != 0u) && (nb_mask[p * NB + nb] != 0u);

    const unsigned ball = __ballot_sync(0xffffffffu, m);
    const int lane = j & 31;
    const int warp = j >> 5;                   // 0..31
    const int wpre = __popc(ball & ((1u << lane) - 1u));

    __shared__ int wsum[32];
    __shared__ int woff[32];
    if (lane == 0) wsum[warp] = __popc(ball);
    __syncthreads();

    if (warp == 0) {
        int v = wsum[lane];
        int s = v;
        #pragma unroll
        for (int d = 1; d < 32; d <<= 1) {
            int t = __shfl_up_sync(0xffffffffu, s, d);
            if (lane >= d) s += t;
        }
        woff[lane] = s - v;                    // exclusive prefix of warp totals
        if (lane == 31) g_n[p] = s;            // total valid count
    }
    __syncthreads();

    if (m) {
        int4 rec;
        rec.x = knn_idx[gk];
        rec.y = __float_as_int(knn_points[gk * 3 + 0]);
        rec.z = __float_as_int(knn_points[gk * 3 + 1]);
        rec.w = __float_as_int(knn_points[gk * 3 + 2]);
        g_rec[p * LL + woff[warp] + wpre] = rec;
    }
}

// ---------------------------------------------------------------------------
// Kernel 2: resample + gather. One warp per output row (p, i).
// Output layout (float32, concatenated flat):
//   [0,              P*M*3)            points
//   [P*M*3,          P*M*3 + P*M*D)    feats
//   [P*M*3 + P*M*D,  end)              mask (1.0f / 0.0f)
// Resample index: single-rounded fp32 floor((i*n)/450); i*n < 2^24 so the
// product is exact and the IEEE divide is exact at integer quotients —
// bit-matches XLA's rewritten (i/M)*n.
// Chain: g_n (L1 broadcast) -> record (L2) -> feat row (L2) -> store.
// ---------------------------------------------------------------------------
__global__ void __launch_bounds__(128) gather_kernel(
    const float* __restrict__ feats,        // [NPTS, D]
    float*       __restrict__ out)
{
    const int p = blockIdx.x;
    const int i = blockIdx.y * 4 + (threadIdx.x >> 5);
    if (i >= MM) return;
    const int lane = threadIdx.x & 31;

    const size_t FEATS_OFF = (size_t)NP * MM * 3;
    const size_t MASK_OFF  = FEATS_OFF + (size_t)NP * MM * DD;
    const size_t row = (size_t)p * MM + i;

    const int n = g_n[p];
    const int nm = (n < MM) ? n : MM;

    float4* dst = (float4*)(out + FEATS_OFF + row * DD);

    if (i < nm) {
        int local;
        if (n > MM) {
            local = __float2int_rd(__fdiv_rn((float)(i * n), (float)MM));
        } else {
            local = i;
        }
        if (local > LL - 1) local = LL - 1;
        if (local < 0) local = 0;

        int4 rec;
        if (lane == 0) rec = g_rec[p * LL + local];
        const int fidx = __shfl_sync(0xffffffffu, rec.x, 0);
        const int pxb  = __shfl_sync(0xffffffffu, rec.y, 0);
        const int pyb  = __shfl_sync(0xffffffffu, rec.z, 0);
        const int pzb  = __shfl_sync(0xffffffffu, rec.w, 0);

        if (lane < 3) {
            const int b = (lane == 0) ? pxb : (lane == 1) ? pyb : pzb;
            out[row * 3 + lane] = __int_as_float(b);
        }
        if (lane == 0) out[MASK_OFF + row] = 1.0f;

        if (fidx >= 0 && fidx < NPTS_C) {
            const float4* src = (const float4*)(feats + (size_t)fidx * DD);
            dst[lane]      = __ldg(src + lane);
            dst[lane + 32] = __ldg(src + lane + 32);
        } else {
            const float4 z = make_float4(0.f, 0.f, 0.f, 0.f);
            dst[lane] = z;
            dst[lane + 32] = z;
        }
    } else {
        if (lane < 3) out[row * 3 + lane] = 0.0f;
        if (lane == 0) out[MASK_OFF + row] = 0.0f;
        const float4 z = make_float4(0.f, 0.f, 0.f, 0.f);
        dst[lane] = z;
        dst[lane + 32] = z;
    }
}

extern "C" void kernel_launch(void* const* d_in, const int* in_sizes, int n_in,
                              void* d_out, int out_size)
{
    // metadata order (= setup_inputs dict order):
    // 0: ref_node_neighbor_mask   (P, NB)        bool -> u32
    // 1: ref_seed_neighbor_indices(P, NB)        int32
    // 2: ref_node_knn_masks       (NNODES, K)    bool -> u32
    // 3: ref_node_knn_points      (NNODES, K, 3) float32
    // 4: ref_node_knn_indices     (NNODES, K)    int32
    // 5: ref_feats_m              (NPTS, D)      float32
    const unsigned int*  nb_mask    = (const unsigned int*)d_in[0];
    const int*           seed_idx   = (const int*)d_in[1];
    const unsigned int*  knn_masks  = (const unsigned int*)d_in[2];
    const float*         knn_points = (const float*)d_in[3];
    const int*           knn_idx    = (const int*)d_in[4];
    const float*         feats      = (const float*)d_in[5];
    float* out = (float*)d_out;

    compact_kernel<<<NP, 1024>>>(nb_mask, seed_idx, knn_masks, knn_idx, knn_points);

    dim3 grid(NP, (MM + 3) / 4);   // 4 warps/block, 1 warp per output row
    gather_kernel<<<grid, 128>>>(feats, out);
}